// round 7
// baseline (speedup 1.0000x reference)
#include <cuda_runtime.h>
#include <cuda_fp16.h>

// In (4,8,262144) f32, NNsites (13,262144) i32, Weights (8,8,16) f32,
// bias (8,8) f32. Output (4,8,262144) f32.
#define NSITES_MAX 262144

// Site-major features, fp16, PRE-SCALED by log2(e). Row = 32 half = 64 B.
// g_T[n][bo] = log2e *  sum_i Wn[o][i]*In[b][i][n]
// g_S[n][bo] = log2e * (sum_i Ws[o][i]*In[b][i][n] + beff[o])
__device__ __align__(256) __half2 g_T[NSITES_MAX * 16];
__device__ __align__(256) __half2 g_S[NSITES_MAX * 16];

__device__ __forceinline__ __half2 u32_as_h2(unsigned v) {
    return *reinterpret_cast<const __half2*>(&v);
}

__device__ __forceinline__ unsigned long long pack_f32x2(float lo, float hi) {
    unsigned long long r;
    asm("mov.b64 %0, {%1, %2};" : "=l"(r) : "f"(lo), "f"(hi));
    return r;
}
__device__ __forceinline__ void unpack_f32x2(unsigned long long v, float& lo, float& hi) {
    asm("mov.b64 {%0, %1}, %2;" : "=f"(lo), "=f"(hi) : "l"(v));
}
// acc = a * b + acc, packed fp32x2 (Blackwell FFMA2)
__device__ __forceinline__ void fma2_f32x2(unsigned long long& acc,
                                           unsigned long long a,
                                           unsigned long long b) {
    asm("fma.rn.f32x2 %0, %1, %2, %0;" : "+l"(acc) : "l"(a), "l"(b));
}
// acc (packed f32x2) += {a, b}
__device__ __forceinline__ void acc_f32x2(unsigned long long& acc, float a, float b) {
    unsigned long long t = pack_f32x2(a, b);
    asm("add.rn.f32x2 %0, %0, %1;" : "+l"(acc) : "l"(t));
}

// ---------------------------------------------------------------------------
// Pass 1: compute BOTH T' and S' (fp16, log2e-scaled), site-major.
// Packed fp32x2 math: lane.lo accumulates T, lane.hi accumulates S.
// In tile stored pre-duplicated {x,x} (u64) so inner loop = LDS.64 + FFMA2.
// 128 sites per CTA, smem row stride 129 (odd) -> conflict-light.
// ---------------------------------------------------------------------------
__global__ __launch_bounds__(256) void pass1_kernel(
    const float* __restrict__ In,      // In[(b*8+i)*N + n]
    const float* __restrict__ W,       // W[j*128 + o*16 + k]
    const float* __restrict__ bias,    // bias[j*8 + o]
    int N)
{
    __shared__ unsigned long long sw2[8][8];        // {wn', ws'} per (o,i)
    __shared__ unsigned long long sbe2[8];          // {0, be'}
    __shared__ unsigned long long sind[32][129];    // {x, x} duplicated

    const int tid  = threadIdx.x;
    const int base = blockIdx.x * 128;
    const float L2E = 1.44269504f;

    if (tid < 64) {
        int o = tid >> 3, i = tid & 7;
        float wn = 0.f, ws = 0.f;
        #pragma unroll
        for (int j = 0; j < 8; j++) {
            ws += W[j * 128 + o * 16 + i];
            wn += W[j * 128 + o * 16 + 8 + i];
        }
        sw2[o][i] = pack_f32x2(wn * L2E, ws * L2E);
        if (i == 0) {
            float be = 0.f;
            #pragma unroll
            for (int j = 0; j < 8; j++) be += bias[j * 8 + o];
            sbe2[o] = pack_f32x2(0.f, be * L2E);
        }
    }
    #pragma unroll
    for (int k = 0; k < 16; k++) {
        int idx = tid + k * 256;
        int r = idx >> 7, c = idx & 127;
        float v = In[r * N + base + c];
        sind[r][c] = pack_f32x2(v, v);
    }
    __syncthreads();

    const int w  = tid >> 5, lane = tid & 31;
    const int j  = lane & 7;                // bo group: 4j..4j+3
    const int b  = j >> 1, o0 = (j & 1) * 4;

    // Weights + init held in registers across the 4-site loop.
    unsigned long long w2[4][8];
    #pragma unroll
    for (int q = 0; q < 4; q++)
        #pragma unroll
        for (int i = 0; i < 8; i++) w2[q][i] = sw2[o0 + q][i];
    unsigned long long init[4];
    #pragma unroll
    for (int q = 0; q < 4; q++) init[q] = sbe2[o0 + q];

    #pragma unroll
    for (int st = 0; st < 4; st++) {
        const int sl = st * 32 + w * 4 + (lane >> 3);

        unsigned long long xd[8];
        #pragma unroll
        for (int i = 0; i < 8; i++) xd[i] = sind[b * 8 + i][sl];

        unsigned long long acc[4];
        #pragma unroll
        for (int q = 0; q < 4; q++) acc[q] = init[q];

        #pragma unroll
        for (int q = 0; q < 4; q++)
            #pragma unroll
            for (int i = 0; i < 8; i++)
                fma2_f32x2(acc[q], w2[q][i], xd[i]);   // lo+=wn*x, hi+=ws*x

        float tv[4], sv[4];
        #pragma unroll
        for (int q = 0; q < 4; q++) unpack_f32x2(acc[q], tv[q], sv[q]);

        __half2 th0 = __floats2half2_rn(tv[0], tv[1]);
        __half2 th1 = __floats2half2_rn(tv[2], tv[3]);
        __half2 sh0 = __floats2half2_rn(sv[0], sv[1]);
        __half2 sh1 = __floats2half2_rn(sv[2], sv[3]);
        uint2 ut = make_uint2(*reinterpret_cast<unsigned*>(&th0),
                              *reinterpret_cast<unsigned*>(&th1));
        uint2 us = make_uint2(*reinterpret_cast<unsigned*>(&sh0),
                              *reinterpret_cast<unsigned*>(&sh1));
        ((uint2*)g_T)[(base + sl) * 8 + j] = ut;
        ((uint2*)g_S)[(base + sl) * 8 + j] = us;
    }
}

// ---------------------------------------------------------------------------
// Pass 2 (UNCHANGED from R6): out[bo][n] = sum_z softplus(S + T[nn])
// log2e-scaled:  sum sp(x) = ln2 * sum max(x',0) + log( prod (1+2^{-|x'|}) )
// NO shared memory, NO barriers. 4 lanes/site, 8 sites/warp, LDG.128 gathers.
// ---------------------------------------------------------------------------
__global__ __launch_bounds__(256, 6) void pass2_kernel(
    const int*   __restrict__ NN,      // NN[z*N + n]
    float*       __restrict__ out,     // out[bo*N + n]
    int N)
{
    const int tid  = threadIdx.x;
    const int base = blockIdx.x * 64;
    const int w    = tid >> 5, lane = tid & 31;
    const int sl   = w * 8 + (lane >> 2);
    const int jj   = lane & 3;              // batch b; bo = jj*8..jj*8+7
    const int n    = base + sl;

    uint4 s4 = ((const uint4*)g_S)[n * 4 + jj];
    __half2 s2[4] = { u32_as_h2(s4.x), u32_as_h2(s4.y),
                      u32_as_h2(s4.z), u32_as_h2(s4.w) };

    int idx[12];
    #pragma unroll
    for (int z = 0; z < 12; z++) idx[z] = NN[(z + 1) * N + n];

    const __half2 one2 = __float2half2_rn(1.f);
    const __half2 m22  = __float2half2_rn(-2.f);
    const uint4* __restrict__ Tp = (const uint4*)g_T;

    __half2 prod[4] = {one2, one2, one2, one2};
    unsigned long long lin[4] = {0ull, 0ull, 0ull, 0ull};

    #pragma unroll
    for (int zc = 0; zc < 3; zc++) {
        uint4 t4[4];
        #pragma unroll
        for (int z = 0; z < 4; z++)
            t4[z] = Tp[idx[zc * 4 + z] * 4 + jj];
        #pragma unroll
        for (int p = 0; p < 2; p++) {
            const uint4& ta = t4[p * 2];
            const uint4& tb = t4[p * 2 + 1];
            unsigned tau[4] = {ta.x, ta.y, ta.z, ta.w};
            unsigned tbu[4] = {tb.x, tb.y, tb.z, tb.w};
            #pragma unroll
            for (int m = 0; m < 4; m++) {
                __half2 tha = u32_as_h2(tau[m]);
                __half2 thb = u32_as_h2(tbu[m]);
                __half2 ra = __hfma2_relu(s2[m], one2, tha);
                __half2 rb = __hfma2_relu(s2[m], one2, thb);
                __half2 ma = __hadd2(__hfma2(ra, m22, tha), s2[m]);
                __half2 mb = __hadd2(__hfma2(rb, m22, thb), s2[m]);
                __half2 e;
                e = h2exp2(ma); prod[m] = __hfma2(prod[m], e, prod[m]);
                e = h2exp2(mb); prod[m] = __hfma2(prod[m], e, prod[m]);
                __half2 rp = __hadd2(ra, rb);
                float2 f = __half22float2(rp);
                acc_f32x2(lin[m], f.x, f.y);
            }
        }
    }

    const float ln2 = 0.69314718f;
    #pragma unroll
    for (int m = 0; m < 4; m++) {
        float lx, ly;
        unpack_f32x2(lin[m], lx, ly);
        float r0 = fmaf(ln2, lx, __logf(__low2float (prod[m])));
        float r1 = fmaf(ln2, ly, __logf(__high2float(prod[m])));
        out[(jj * 8 + 2 * m + 0) * N + n] = r0;
        out[(jj * 8 + 2 * m + 1) * N + n] = r1;
    }
}

extern "C" void kernel_launch(void* const* d_in, const int* in_sizes, int n_in,
                              void* d_out, int out_size)
{
    const float* In   = (const float*)d_in[0];
    const int*   NN   = (const int*)  d_in[1];
    const float* W    = (const float*)d_in[2];
    const float* bias = (const float*)d_in[3];
    float*       out  = (float*)d_out;

    const int N = in_sizes[0] / 32;

    pass1_kernel<<<N / 128, 256>>>(In, W, bias, N);
    pass2_kernel<<<N / 64, 256>>>(NN, out, N);
}